// round 3
// baseline (speedup 1.0000x reference)
#include <cuda_runtime.h>
#include <cuda_bf16.h>
#include <cstdint>

#define CUT 512
#define IMG_H 4096
#define IMG_W 4096
#define HW ((size_t)IMG_H * IMG_W)
#define PLANE ((size_t)CUT * CUT)
#define IMG_STRIDE ((size_t)3 * CUT * CUT)

// Each thread computes TWO output pixels: (oy, ox) and (oy+8, ox).
// x-interp state is shared; 24 independent LDGs per thread for MLP.
__global__ __launch_bounds__(256, 6)
void dango_cutouts_kernel(const float* __restrict__ img,
                          const int* __restrict__ sizes,
                          const int* __restrict__ offy,
                          const int* __restrict__ offx,
                          float* __restrict__ out) {
    const int ox  = blockIdx.x * 32 + threadIdx.x;        // 0..511
    const int oyA = blockIdx.y * 16 + threadIdx.y;        // 0..511 (two halves)
    const int oyB = oyA + 8;
    const int z   = blockIdx.z;                           // 0 = overview, 1..12 = inner crops

    int size, ioy, iox;
    if (z == 0) { size = IMG_W < IMG_H ? IMG_W : IMG_H; ioy = 0; iox = 0; }
    else        { size = sizes[z - 1]; ioy = offy[z - 1]; iox = offx[z - 1]; }

    const float s     = (float)size;
    const float offyf = (float)ioy;
    const float offxf = (float)iox;
    const float ymax  = offyf + s - 1.0f;
    const int   ylim  = ioy + size - 1;

    // ---- shared x-axis interpolation state ----
    float tx = ((float)ox + 0.5f) * s / 512.0f - 0.5f;
    float x  = offxf + tx;
    x = fminf(fmaxf(x, offxf), offxf + s - 1.0f);
    int   x0 = (int)floorf(x);
    int   x1 = min(x0 + 1, iox + size - 1);
    float wx = x - (float)x0;

    // ---- per-pixel y state ----
    float yA = offyf + (((float)oyA + 0.5f) * s / 512.0f - 0.5f);
    yA = fminf(fmaxf(yA, offyf), ymax);
    int   y0A = (int)floorf(yA);
    int   y1A = min(y0A + 1, ylim);
    float wyA = yA - (float)y0A;

    float yB = offyf + (((float)oyB + 0.5f) * s / 512.0f - 0.5f);
    yB = fminf(fmaxf(yB, offyf), ymax);
    int   y0B = (int)floorf(yB);
    int   y1B = min(y0B + 1, ylim);
    float wyB = yB - (float)y0B;

    const size_t r0A = (size_t)y0A * IMG_W;
    const size_t r1A = (size_t)y1A * IMG_W;
    const size_t r0B = (size_t)y0B * IMG_W;
    const size_t r1B = (size_t)y1B * IMG_W;

    // ---- batch all 24 loads up front for max MLP ----
    float vA[3][4], vB[3][4];
    #pragma unroll
    for (int c = 0; c < 3; c++) {
        const float* __restrict__ p = img + (size_t)c * HW;
        vA[c][0] = __ldg(p + r0A + x0);
        vA[c][1] = __ldg(p + r0A + x1);
        vA[c][2] = __ldg(p + r1A + x0);
        vA[c][3] = __ldg(p + r1A + x1);
        vB[c][0] = __ldg(p + r0B + x0);
        vB[c][1] = __ldg(p + r0B + x1);
        vB[c][2] = __ldg(p + r1B + x0);
        vB[c][3] = __ldg(p + r1B + x1);
    }

    float rgbA[3], rgbB[3];
    #pragma unroll
    for (int c = 0; c < 3; c++) {
        float topA = vA[c][0] * (1.0f - wx) + vA[c][1] * wx;
        float botA = vA[c][2] * (1.0f - wx) + vA[c][3] * wx;
        rgbA[c] = topA * (1.0f - wyA) + botA * wyA;
        float topB = vB[c][0] * (1.0f - wx) + vB[c][1] * wx;
        float botB = vB[c][2] * (1.0f - wx) + vB[c][3] * wx;
        rgbB[c] = topB * (1.0f - wyB) + botB * wyB;
    }
    const float grayA = 0.2989f * rgbA[0] + 0.587f * rgbA[1] + 0.114f * rgbA[2];
    const float grayB = 0.2989f * rgbB[0] + 0.587f * rgbB[1] + 0.114f * rgbB[2];

    const size_t pixA = (size_t)oyA * CUT + ox;
    const size_t pixB = (size_t)oyB * CUT + ox;

    if (z == 0) {
        // One full-resize sample feeds all 4 overview images.
        // flipped(y, x) = full(y, 511-x)
        const size_t pixfA = (size_t)oyA * CUT + (CUT - 1 - ox);
        const size_t pixfB = (size_t)oyB * CUT + (CUT - 1 - ox);
        #pragma unroll
        for (int c = 0; c < 3; c++) {
            out[0 * IMG_STRIDE + c * PLANE + pixA]  = rgbA[c];
            out[1 * IMG_STRIDE + c * PLANE + pixA]  = grayA;
            out[2 * IMG_STRIDE + c * PLANE + pixfA] = rgbA[c];
            out[3 * IMG_STRIDE + c * PLANE + pixfA] = grayA;
            out[0 * IMG_STRIDE + c * PLANE + pixB]  = rgbB[c];
            out[1 * IMG_STRIDE + c * PLANE + pixB]  = grayB;
            out[2 * IMG_STRIDE + c * PLANE + pixfB] = rgbB[c];
            out[3 * IMG_STRIDE + c * PLANE + pixfB] = grayB;
        }
    } else {
        const size_t base = (size_t)(3 + z) * IMG_STRIDE;  // output image 4 + (z-1)
        if (z == 1) {
            #pragma unroll
            for (int c = 0; c < 3; c++) {
                out[base + c * PLANE + pixA] = grayA;
                out[base + c * PLANE + pixB] = grayB;
            }
        } else {
            #pragma unroll
            for (int c = 0; c < 3; c++) {
                out[base + c * PLANE + pixA] = rgbA[c];
                out[base + c * PLANE + pixB] = rgbB[c];
            }
        }
    }
}

extern "C" void kernel_launch(void* const* d_in, const int* in_sizes, int n_in,
                              void* d_out, int out_size) {
    const float* img   = (const float*)d_in[0];   // (1,3,4096,4096) fp32
    // d_in[1] = t (unused scalar)
    const int*   sizes = (const int*)d_in[2];     // (12,)
    const int*   offy  = (const int*)d_in[3];     // (12,)
    const int*   offx  = (const int*)d_in[4];     // (12,)
    float* out = (float*)d_out;                   // (16,3,512,512) fp32

    dim3 block(32, 8, 1);
    dim3 grid(CUT / 32, CUT / 16, 13);  // 2 y-pixels per thread
    dango_cutouts_kernel<<<grid, block>>>(img, sizes, offy, offx, out);
}

// round 4
// speedup vs baseline: 1.0894x; 1.0894x over previous
#include <cuda_runtime.h>
#include <cuda_bf16.h>
#include <cstdint>

#define CUT 512
#define IMG_W 4096
#define HW (4096u * 4096u)           // 16.7M elements per channel (fits uint32)
#define PLANE (512u * 512u)
#define IMG_STRIDE (3u * 512u * 512u)

__global__ __launch_bounds__(128)
void dango_cutouts_kernel(const float* __restrict__ img,
                          const int* __restrict__ sizes,
                          const int* __restrict__ offy,
                          const int* __restrict__ offx,
                          float* __restrict__ out) {
    const int ox = blockIdx.x * 32 + threadIdx.x;   // 0..511
    const int oy = blockIdx.y * 4  + threadIdx.y;   // 0..511
    const int z  = blockIdx.z;                      // 0 = overview, 1..12 = inner crops

    int size, ioy, iox;
    if (z == 0) { size = 4096; ioy = 0; iox = 0; }
    else        { size = sizes[z - 1]; ioy = offy[z - 1]; iox = offx[z - 1]; }

    const float s     = (float)size;
    const float offyf = (float)ioy;
    const float offxf = (float)iox;

    // t = (i + 0.5) * s / 512 - 0.5  (pow2 scale: exact)
    float y = offyf + (((float)oy + 0.5f) * s * (1.0f / 512.0f) - 0.5f);
    y = fminf(fmaxf(y, offyf), offyf + s - 1.0f);
    int   y0 = (int)floorf(y);
    float wy = y - (float)y0;
    int   dy = (y0 + 1 <= ioy + size - 1) ? 1 : 0;   // y1 - y0

    float x = offxf + (((float)ox + 0.5f) * s * (1.0f / 512.0f) - 0.5f);
    x = fminf(fmaxf(x, offxf), offxf + s - 1.0f);
    int   x0 = (int)floorf(x);
    float wx = x - (float)x0;
    int   dx = (x0 + 1 <= iox + size - 1) ? 1 : 0;   // x1 - x0

    // 32-bit element offsets: base tap + deltas
    const unsigned base = (unsigned)y0 * (unsigned)IMG_W + (unsigned)x0;
    const unsigned drow = (unsigned)dy * (unsigned)IMG_W;

    // ---- batch the 12 loads ----
    float v[3][4];
    #pragma unroll
    for (int c = 0; c < 3; c++) {
        const float* __restrict__ p = img + (unsigned)c * HW + base;
        v[c][0] = __ldg(p);
        v[c][1] = __ldg(p + dx);
        v[c][2] = __ldg(p + drow);
        v[c][3] = __ldg(p + drow + dx);
    }

    float rgb[3];
    #pragma unroll
    for (int c = 0; c < 3; c++) {
        float top = v[c][0] * (1.0f - wx) + v[c][1] * wx;
        float bot = v[c][2] * (1.0f - wx) + v[c][3] * wx;
        rgb[c] = top * (1.0f - wy) + bot * wy;
    }
    const float gray = 0.2989f * rgb[0] + 0.587f * rgb[1] + 0.114f * rgb[2];

    const unsigned pix = (unsigned)oy * (unsigned)CUT + (unsigned)ox;

    if (z == 0) {
        // One full-resize sample feeds all 4 overview images.
        // flipped(y, x) = full(y, 511-x)
        const unsigned pixf = (unsigned)oy * (unsigned)CUT + (unsigned)(CUT - 1 - ox);
        #pragma unroll
        for (int c = 0; c < 3; c++) {
            out[0u * IMG_STRIDE + (unsigned)c * PLANE + pix]  = rgb[c];
            out[1u * IMG_STRIDE + (unsigned)c * PLANE + pix]  = gray;
            out[2u * IMG_STRIDE + (unsigned)c * PLANE + pixf] = rgb[c];
            out[3u * IMG_STRIDE + (unsigned)c * PLANE + pixf] = gray;
        }
    } else {
        const unsigned base_o = (unsigned)(3 + z) * IMG_STRIDE;  // output image 4 + (z-1)
        if (z == 1) {
            #pragma unroll
            for (int c = 0; c < 3; c++)
                out[base_o + (unsigned)c * PLANE + pix] = gray;
        } else {
            #pragma unroll
            for (int c = 0; c < 3; c++)
                out[base_o + (unsigned)c * PLANE + pix] = rgb[c];
        }
    }
}

extern "C" void kernel_launch(void* const* d_in, const int* in_sizes, int n_in,
                              void* d_out, int out_size) {
    const float* img   = (const float*)d_in[0];   // (1,3,4096,4096) fp32
    // d_in[1] = t (unused scalar)
    const int*   sizes = (const int*)d_in[2];     // (12,)
    const int*   offy  = (const int*)d_in[3];     // (12,)
    const int*   offx  = (const int*)d_in[4];     // (12,)
    float* out = (float*)d_out;                   // (16,3,512,512) fp32

    dim3 block(32, 4, 1);
    dim3 grid(CUT / 32, CUT / 4, 13);  // 128-thread blocks for finer scheduling
    dango_cutouts_kernel<<<grid, block>>>(img, sizes, offy, offx, out);
}

// round 6
// speedup vs baseline: 1.1216x; 1.0295x over previous
#include <cuda_runtime.h>
#include <cuda_bf16.h>
#include <cstdint>

#define CUT 512
#define IMG_W 4096
#define HW (4096u * 4096u)
#define PLANE (512u * 512u)
#define IMG_STRIDE (3u * 512u * 512u)

// Block = 128 consecutive x-pixels of ONE output row. The 4 warps of a block
// gather from the SAME two input rows per channel -> long contiguous DRAM
// bursts instead of interleaved short spans. Stores are evict-first (__stcs)
// so the 50MB output stream doesn't evict source data from L2.
__global__ __launch_bounds__(128)
void dango_cutouts_kernel(const float* __restrict__ img,
                          const int* __restrict__ sizes,
                          const int* __restrict__ offy,
                          const int* __restrict__ offx,
                          float* __restrict__ out) {
    const int ox = blockIdx.x * 128 + threadIdx.x;  // 0..511
    const int oy = blockIdx.y;                      // 0..511
    const int z  = blockIdx.z;                      // 0 = overview, 1..12 = inner crops

    int size, ioy, iox;
    if (z == 0) { size = 4096; ioy = 0; iox = 0; }
    else        { size = sizes[z - 1]; ioy = offy[z - 1]; iox = offx[z - 1]; }

    const float s     = (float)size;
    const float offyf = (float)ioy;
    const float offxf = (float)iox;

    // t = (i + 0.5) * s / 512 - 0.5  (pow2 scale: exact)
    float y = offyf + (((float)oy + 0.5f) * s * (1.0f / 512.0f) - 0.5f);
    y = fminf(fmaxf(y, offyf), offyf + s - 1.0f);
    int   y0 = (int)floorf(y);
    float wy = y - (float)y0;
    int   dy = (y0 + 1 <= ioy + size - 1) ? 1 : 0;   // y1 - y0

    float x = offxf + (((float)ox + 0.5f) * s * (1.0f / 512.0f) - 0.5f);
    x = fminf(fmaxf(x, offxf), offxf + s - 1.0f);
    int   x0 = (int)floorf(x);
    float wx = x - (float)x0;
    int   dx = (x0 + 1 <= iox + size - 1) ? 1 : 0;   // x1 - x0

    const unsigned base = (unsigned)y0 * (unsigned)IMG_W + (unsigned)x0;
    const unsigned drow = (unsigned)dy * (unsigned)IMG_W;

    // ---- batch the 12 loads ----
    float v[3][4];
    #pragma unroll
    for (int c = 0; c < 3; c++) {
        const float* __restrict__ p = img + (unsigned)c * HW + base;
        v[c][0] = __ldg(p);
        v[c][1] = __ldg(p + dx);
        v[c][2] = __ldg(p + drow);
        v[c][3] = __ldg(p + drow + dx);
    }

    float rgb[3];
    #pragma unroll
    for (int c = 0; c < 3; c++) {
        float top = v[c][0] * (1.0f - wx) + v[c][1] * wx;
        float bot = v[c][2] * (1.0f - wx) + v[c][3] * wx;
        rgb[c] = top * (1.0f - wy) + bot * wy;
    }
    const float gray = 0.2989f * rgb[0] + 0.587f * rgb[1] + 0.114f * rgb[2];

    const unsigned pix = (unsigned)oy * (unsigned)CUT + (unsigned)ox;

    if (z == 0) {
        // One full-resize sample feeds all 4 overview images.
        // flipped(y, x) = full(y, 511-x)
        const unsigned pixf = (unsigned)oy * (unsigned)CUT + (unsigned)(CUT - 1 - ox);
        #pragma unroll
        for (int c = 0; c < 3; c++) {
            __stcs(out + 0u * IMG_STRIDE + (unsigned)c * PLANE + pix,  rgb[c]);
            __stcs(out + 1u * IMG_STRIDE + (unsigned)c * PLANE + pix,  gray);
            __stcs(out + 2u * IMG_STRIDE + (unsigned)c * PLANE + pixf, rgb[c]);
            __stcs(out + 3u * IMG_STRIDE + (unsigned)c * PLANE + pixf, gray);
        }
    } else {
        const unsigned base_o = (unsigned)(3 + z) * IMG_STRIDE;  // output image 4 + (z-1)
        if (z == 1) {
            #pragma unroll
            for (int c = 0; c < 3; c++)
                __stcs(out + base_o + (unsigned)c * PLANE + pix, gray);
        } else {
            #pragma unroll
            for (int c = 0; c < 3; c++)
                __stcs(out + base_o + (unsigned)c * PLANE + pix, rgb[c]);
        }
    }
}

extern "C" void kernel_launch(void* const* d_in, const int* in_sizes, int n_in,
                              void* d_out, int out_size) {
    const float* img   = (const float*)d_in[0];   // (1,3,4096,4096) fp32
    // d_in[1] = t (unused scalar)
    const int*   sizes = (const int*)d_in[2];     // (12,)
    const int*   offy  = (const int*)d_in[3];     // (12,)
    const int*   offx  = (const int*)d_in[4];     // (12,)
    float* out = (float*)d_out;                   // (16,3,512,512) fp32

    dim3 block(128, 1, 1);
    dim3 grid(CUT / 128, CUT, 13);  // block = 128-px strip of one output row
    dango_cutouts_kernel<<<grid, block>>>(img, sizes, offy, offx, out);
}